// round 9
// baseline (speedup 1.0000x reference)
#include <cuda_runtime.h>

// WaveletLayer fused: db2 DWT -> scale -> inverse DWT -> ReLU, fully collapsed.
//
// QMF identity (hi[i] = (-1)^i lo[3-i]) collapses the chain to, per input
// pair (u,v) = (x[2m], x[2m+1]), with t = sqrt(3)/4:
//   p = 0.75u - t*v,  q = u - p
//   r = 0.25v - t*u,  s = v - r
//   out[2m]   = relu(k[m]*p + k[m+1]*q)
//   out[2m+1] = relu(k[m]*r + k[m+1]*s)
// Boundary/padding contributions cancel identically.
//
// R9: L2 working-set engineering. Cacheable reads x (64MB) + K (33.5MB)
// = 97.5MB fit in the 126MB L2 across graph replays; out is written
// evict-first (__stcs) so it doesn't thrash them. x uses DEFAULT caching
// (R8's __ldcs wrongly marked it evict-first and forced DRAM re-streams).
// Same R8 shape otherwise: one 512-thread block per row, <=32 regs.

#define NCOL 4096
#define LOUT 2049
#define NT   512

__global__ __launch_bounds__(NT) void wavelet_fused_kernel(
    const float* __restrict__ x,
    const float* __restrict__ kern,
    float* __restrict__ out)
{
    const int row  = blockIdx.x;
    const int m0   = threadIdx.x * 4;     // first pair index (0..2044)
    const int base = 2 * m0;              // first output column

    // x[base .. base+7]: two aligned cached float4 loads
    const float4* x4 = reinterpret_cast<const float4*>(x + (size_t)row * NCOL + base);
    float4 X0 = x4[0];
    float4 X1 = x4[1];

    // K window K[m0..m0+4]: block-uniform misalignment d = row & 3,
    // covered by 2 aligned float4 loads + uniform select.
    // (Tail-safe: last row has d=3, read ends exactly at kern's last element.)
    const int w = LOUT * row + m0;
    const int d = w & 3;
    const float4* kp = reinterpret_cast<const float4*>(kern + (w - d));
    float4 F0 = kp[0];
    float4 F1 = kp[1];
    float k0, k1, k2, k3, k4;
    if (d == 0)      { k0 = F0.x; k1 = F0.y; k2 = F0.z; k3 = F0.w; k4 = F1.x; }
    else if (d == 1) { k0 = F0.y; k1 = F0.z; k2 = F0.w; k3 = F1.x; k4 = F1.y; }
    else if (d == 2) { k0 = F0.z; k1 = F0.w; k2 = F1.x; k3 = F1.y; k4 = F1.z; }
    else             { k0 = F0.w; k1 = F1.x; k2 = F1.y; k3 = F1.z; k4 = F1.w; }

    const float T = 0.43301270189221932f;  // sqrt(3)/4

    float u, v, p, q, rr, ss;
    float4 r0, r1;

    u = X0.x; v = X0.y;
    p = fmaf(-T, v, 0.75f * u); q = u - p;
    rr = fmaf(-T, u, 0.25f * v); ss = v - rr;
    r0.x = fmaxf(fmaf(k1, q,  k0 * p),  0.0f);
    r0.y = fmaxf(fmaf(k1, ss, k0 * rr), 0.0f);

    u = X0.z; v = X0.w;
    p = fmaf(-T, v, 0.75f * u); q = u - p;
    rr = fmaf(-T, u, 0.25f * v); ss = v - rr;
    r0.z = fmaxf(fmaf(k2, q,  k1 * p),  0.0f);
    r0.w = fmaxf(fmaf(k2, ss, k1 * rr), 0.0f);

    u = X1.x; v = X1.y;
    p = fmaf(-T, v, 0.75f * u); q = u - p;
    rr = fmaf(-T, u, 0.25f * v); ss = v - rr;
    r1.x = fmaxf(fmaf(k3, q,  k2 * p),  0.0f);
    r1.y = fmaxf(fmaf(k3, ss, k2 * rr), 0.0f);

    u = X1.z; v = X1.w;
    p = fmaf(-T, v, 0.75f * u); q = u - p;
    rr = fmaf(-T, u, 0.25f * v); ss = v - rr;
    r1.z = fmaxf(fmaf(k4, q,  k3 * p),  0.0f);
    r1.w = fmaxf(fmaf(k4, ss, k3 * rr), 0.0f);

    float4* o4 = reinterpret_cast<float4*>(out + (size_t)row * NCOL + base);
    __stcs(o4,     r0);
    __stcs(o4 + 1, r1);
}

extern "C" void kernel_launch(void* const* d_in, const int* in_sizes, int n_in,
                              void* d_out, int out_size)
{
    const float* x    = (const float*)d_in[0];
    const float* kern = (const float*)d_in[1];
    float*       out  = (float*)d_out;

    wavelet_fused_kernel<<<4096, NT>>>(x, kern, out);  // one block per row
}

// round 10
// speedup vs baseline: 1.0276x; 1.0276x over previous
#include <cuda_runtime.h>

// WaveletLayer fused: db2 DWT -> scale -> inverse DWT -> ReLU, fully collapsed.
//
// QMF identity (hi[i] = (-1)^i lo[3-i]) collapses the chain to, per input
// pair (u,v) = (x[2m], x[2m+1]), with t = sqrt(3)/4:
//   p = 0.75u - t*v,  q = u - p
//   r = 0.25v - t*u,  s = v - r
//   out[2m]   = relu(k[m]*p + k[m+1]*q)
//   out[2m+1] = relu(k[m]*r + k[m+1]*s)
// Boundary/padding contributions cancel identically.
//
// R10: L2 residency split across graph replays:
//   - x (64MB): pure stream, __ldcs evict-first (R8-validated: lowers DRAM traffic)
//   - K (33.5MB) + out (64MB) = 97.5MB < 126MB L2: keep resident.
//     out is rewritten every replay -> resident dirty lines never writeback.
//     => default cacheable stores (NO __stcs), default K loads.
// Shape identical to R8: one 512-thread block per row, <=32 regs.

#define NCOL 4096
#define LOUT 2049
#define NT   512

__global__ __launch_bounds__(NT) void wavelet_fused_kernel(
    const float* __restrict__ x,
    const float* __restrict__ kern,
    float* __restrict__ out)
{
    const int row  = blockIdx.x;
    const int m0   = threadIdx.x * 4;     // first pair index (0..2044)
    const int base = 2 * m0;              // first output column

    // x[base .. base+7]: two aligned streaming (evict-first) float4 loads
    const float4* x4 = reinterpret_cast<const float4*>(x + (size_t)row * NCOL + base);
    float4 X0 = __ldcs(x4);
    float4 X1 = __ldcs(x4 + 1);

    // K window K[m0..m0+4]: block-uniform misalignment d = row & 3,
    // covered by 2 aligned float4 loads + uniform select.
    // (Tail-safe: last row has d=3, read ends exactly at kern's last element.)
    const int w = LOUT * row + m0;
    const int d = w & 3;
    const float4* kp = reinterpret_cast<const float4*>(kern + (w - d));
    float4 F0 = kp[0];
    float4 F1 = kp[1];
    float k0, k1, k2, k3, k4;
    if (d == 0)      { k0 = F0.x; k1 = F0.y; k2 = F0.z; k3 = F0.w; k4 = F1.x; }
    else if (d == 1) { k0 = F0.y; k1 = F0.z; k2 = F0.w; k3 = F1.x; k4 = F1.y; }
    else if (d == 2) { k0 = F0.z; k1 = F0.w; k2 = F1.x; k3 = F1.y; k4 = F1.z; }
    else             { k0 = F0.w; k1 = F1.x; k2 = F1.y; k3 = F1.z; k4 = F1.w; }

    const float T = 0.43301270189221932f;  // sqrt(3)/4

    float u, v, p, q, rr, ss;
    float4 r0, r1;

    u = X0.x; v = X0.y;
    p = fmaf(-T, v, 0.75f * u); q = u - p;
    rr = fmaf(-T, u, 0.25f * v); ss = v - rr;
    r0.x = fmaxf(fmaf(k1, q,  k0 * p),  0.0f);
    r0.y = fmaxf(fmaf(k1, ss, k0 * rr), 0.0f);

    u = X0.z; v = X0.w;
    p = fmaf(-T, v, 0.75f * u); q = u - p;
    rr = fmaf(-T, u, 0.25f * v); ss = v - rr;
    r0.z = fmaxf(fmaf(k2, q,  k1 * p),  0.0f);
    r0.w = fmaxf(fmaf(k2, ss, k1 * rr), 0.0f);

    u = X1.x; v = X1.y;
    p = fmaf(-T, v, 0.75f * u); q = u - p;
    rr = fmaf(-T, u, 0.25f * v); ss = v - rr;
    r1.x = fmaxf(fmaf(k3, q,  k2 * p),  0.0f);
    r1.y = fmaxf(fmaf(k3, ss, k2 * rr), 0.0f);

    u = X1.z; v = X1.w;
    p = fmaf(-T, v, 0.75f * u); q = u - p;
    rr = fmaf(-T, u, 0.25f * v); ss = v - rr;
    r1.z = fmaxf(fmaf(k4, q,  k3 * p),  0.0f);
    r1.w = fmaxf(fmaf(k4, ss, k3 * rr), 0.0f);

    // Default cacheable stores: keep out resident in L2 across replays.
    float4* o4 = reinterpret_cast<float4*>(out + (size_t)row * NCOL + base);
    o4[0] = r0;
    o4[1] = r1;
}

extern "C" void kernel_launch(void* const* d_in, const int* in_sizes, int n_in,
                              void* d_out, int out_size)
{
    const float* x    = (const float*)d_in[0];
    const float* kern = (const float*)d_in[1];
    float*       out  = (float*)d_out;

    wavelet_fused_kernel<<<4096, NT>>>(x, kern, out);  // one block per row
}

// round 11
// speedup vs baseline: 1.2460x; 1.2125x over previous
#include <cuda_runtime.h>

// WaveletLayer fused: db2 DWT -> scale -> inverse DWT -> ReLU, fully collapsed.
//
// QMF identity (hi[i] = (-1)^i lo[3-i]) collapses the chain to, per input
// pair (u,v) = (x[2m], x[2m+1]), with t = sqrt(3)/4:
//   p = 0.75u - t*v,  q = u - p
//   r = 0.25v - t*u,  s = v - r
//   out[2m]   = relu(k[m]*p + k[m+1]*q)
//   out[2m+1] = relu(k[m]*r + k[m+1]*s)
// Boundary/padding contributions cancel identically.
//
// R11 = R8 (best validated config: __ldcs x stream, __stcs out stream,
// K default-cached, one 512-thread block per row, <=34 regs) plus K-load
// dedup: adjacent threads' aligned K float4s overlap such that thread i's
// second K vector IS thread i+1's first -> fetch it with 4 shfl_down
// instead of a second LDG.128 (lane 31 does the real load). Cuts L1 read
// wavefronts ~17% and shrinks the front load batch.

#define NCOL 4096
#define LOUT 2049
#define NT   512
#define FULL 0xffffffffu

__global__ __launch_bounds__(NT) void wavelet_fused_kernel(
    const float* __restrict__ x,
    const float* __restrict__ kern,
    float* __restrict__ out)
{
    const int row  = blockIdx.x;
    const int m0   = threadIdx.x * 4;     // first pair index (0..2044)
    const int base = 2 * m0;              // first output column
    const int lane = threadIdx.x & 31;

    // x[base .. base+7]: two aligned streaming (evict-first) float4 loads
    const float4* x4 = reinterpret_cast<const float4*>(x + (size_t)row * NCOL + base);
    float4 X0 = __ldcs(x4);
    float4 X1 = __ldcs(x4 + 1);

    // K window K[m0..m0+4]: block-uniform misalignment d = row & 3.
    // Aligned coverage = two float4s [w-d, w-d+8). Adjacent threads' aligned
    // pointers differ by exactly 4 floats, so F1(thread i) == F0(thread i+1):
    // load F0 only, build F1 by shuffle; lane 31 loads its F1 directly.
    // (Tail-safe: last row has d=3, F1 read ends exactly at kern's last elem.)
    const int w = LOUT * row + m0;
    const int d = w & 3;
    const float4* kp = reinterpret_cast<const float4*>(kern + (w - d));
    float4 F0 = kp[0];

    float4 F1;
    F1.x = __shfl_down_sync(FULL, F0.x, 1);
    F1.y = __shfl_down_sync(FULL, F0.y, 1);
    F1.z = __shfl_down_sync(FULL, F0.z, 1);
    F1.w = __shfl_down_sync(FULL, F0.w, 1);
    if (lane == 31) F1 = kp[1];

    float k0, k1, k2, k3, k4;
    if (d == 0)      { k0 = F0.x; k1 = F0.y; k2 = F0.z; k3 = F0.w; k4 = F1.x; }
    else if (d == 1) { k0 = F0.y; k1 = F0.z; k2 = F0.w; k3 = F1.x; k4 = F1.y; }
    else if (d == 2) { k0 = F0.z; k1 = F0.w; k2 = F1.x; k3 = F1.y; k4 = F1.z; }
    else             { k0 = F0.w; k1 = F1.x; k2 = F1.y; k3 = F1.z; k4 = F1.w; }

    const float T = 0.43301270189221932f;  // sqrt(3)/4

    float u, v, p, q, rr, ss;
    float4 r0, r1;

    u = X0.x; v = X0.y;
    p = fmaf(-T, v, 0.75f * u); q = u - p;
    rr = fmaf(-T, u, 0.25f * v); ss = v - rr;
    r0.x = fmaxf(fmaf(k1, q,  k0 * p),  0.0f);
    r0.y = fmaxf(fmaf(k1, ss, k0 * rr), 0.0f);

    u = X0.z; v = X0.w;
    p = fmaf(-T, v, 0.75f * u); q = u - p;
    rr = fmaf(-T, u, 0.25f * v); ss = v - rr;
    r0.z = fmaxf(fmaf(k2, q,  k1 * p),  0.0f);
    r0.w = fmaxf(fmaf(k2, ss, k1 * rr), 0.0f);

    u = X1.x; v = X1.y;
    p = fmaf(-T, v, 0.75f * u); q = u - p;
    rr = fmaf(-T, u, 0.25f * v); ss = v - rr;
    r1.x = fmaxf(fmaf(k3, q,  k2 * p),  0.0f);
    r1.y = fmaxf(fmaf(k3, ss, k2 * rr), 0.0f);

    u = X1.z; v = X1.w;
    p = fmaf(-T, v, 0.75f * u); q = u - p;
    rr = fmaf(-T, u, 0.25f * v); ss = v - rr;
    r1.z = fmaxf(fmaf(k4, q,  k3 * p),  0.0f);
    r1.w = fmaxf(fmaf(k4, ss, k3 * rr), 0.0f);

    float4* o4 = reinterpret_cast<float4*>(out + (size_t)row * NCOL + base);
    __stcs(o4,     r0);
    __stcs(o4 + 1, r1);
}

extern "C" void kernel_launch(void* const* d_in, const int* in_sizes, int n_in,
                              void* d_out, int out_size)
{
    const float* x    = (const float*)d_in[0];
    const float* kern = (const float*)d_in[1];
    float*       out  = (float*)d_out;

    wavelet_fused_kernel<<<4096, NT>>>(x, kern, out);  // one block per row
}